// round 15
// baseline (speedup 1.0000x reference)
#include <cuda_runtime.h>
#include <cuda_fp16.h>
#include <cstdint>

// ---------------------------------------------------------------- constants
#define D_Z     1024
#define D_MODEL 4096
#define M_ROWS  16384
#define EPS     1e-5f

#define BM 128
#define BN 128
#define BK 64
#define KITERS (D_Z / BK)      // 16
#define STAGES 3

#define LDA 72                  // 64 + 8 pad (fp16): conflict-free ldmatrix
#define LDB 136                 // 128 + 8 pad
#define A_STAGE_B (BM * LDA * 2)          // 18432 B
#define B_STAGE_B (BK * LDB * 2)          // 17408 B
#define STAGE_B   (A_STAGE_B + B_STAGE_B) // 35840 B
#define SMEM_TOTAL (STAGES * STAGE_B)     // 107520 B -> 2 CTAs/SM

#define LN_BLOCKS   (M_ROWS / 8)          // 2048 (8 rows per block)
#define WCONV_BLOCKS 1024

// scratch (allocation-free rule: device globals)
__device__ __half g_zn[(size_t)M_ROWS * D_Z];     // LN output fp16 [M,K]
__device__ __half g_wb[(size_t)D_Z * D_MODEL];    // W fp16 [K,N]

// ---------------------------------------------------------------- K1: merged prep
__global__ __launch_bounds__(256) void prep_kernel(const float* __restrict__ z,
                                                   const float* __restrict__ gamma,
                                                   const float* __restrict__ beta,
                                                   const float* __restrict__ W) {
    int blk = blockIdx.x;
    int t   = threadIdx.x;

    if (blk >= LN_BLOCKS) {
        size_t base = (size_t)(blk - LN_BLOCKS) * 1024 + t;
        __half2* dst = (__half2*)g_wb;
        #pragma unroll
        for (int u = 0; u < 4; u++) {
            size_t i = base + (size_t)u * 256;
            float4 v = ((const float4*)W)[i];
            dst[i * 2 + 0] = __floats2half2_rn(v.x, v.y);
            dst[i * 2 + 1] = __floats2half2_rn(v.z, v.w);
        }
        return;
    }

    // ---- warp-per-row LayerNorm (no block barriers)
    int wid  = t >> 5;
    int lane = t & 31;
    int row  = blk * 8 + wid;

    const float4* zp = (const float4*)(z + (size_t)row * D_Z);
    float4 v[8];
    #pragma unroll
    for (int c = 0; c < 8; c++) v[c] = zp[lane + c * 32];

    float s = 0.f, ss = 0.f;
    #pragma unroll
    for (int c = 0; c < 8; c++) {
        s  += v[c].x + v[c].y + v[c].z + v[c].w;
        ss += v[c].x * v[c].x + v[c].y * v[c].y + v[c].z * v[c].z + v[c].w * v[c].w;
    }
    #pragma unroll
    for (int o = 16; o > 0; o >>= 1) {
        s  += __shfl_xor_sync(0xffffffffu, s, o);
        ss += __shfl_xor_sync(0xffffffffu, ss, o);
    }
    float mu   = s * (1.0f / D_Z);
    float var  = ss * (1.0f / D_Z) - mu * mu;
    float rstd = rsqrtf(var + EPS);

    const float4* gp = (const float4*)gamma;
    const float4* bp = (const float4*)beta;
    uint2* dst = (uint2*)(g_zn + (size_t)row * D_Z);
    #pragma unroll
    for (int c = 0; c < 8; c++) {
        float4 g = gp[lane + c * 32];
        float4 b = bp[lane + c * 32];
        float o0 = (v[c].x - mu) * rstd * g.x + b.x;
        float o1 = (v[c].y - mu) * rstd * g.y + b.y;
        float o2 = (v[c].z - mu) * rstd * g.z + b.z;
        float o3 = (v[c].w - mu) * rstd * g.w + b.w;
        __half2 h0 = __floats2half2_rn(o0, o1);
        __half2 h1 = __floats2half2_rn(o2, o3);
        uint2 pack;
        pack.x = *(uint32_t*)&h0;
        pack.y = *(uint32_t*)&h1;
        dst[lane + c * 32] = pack;
    }
}

// ---------------------------------------------------------------- PTX wrappers
__device__ __forceinline__ void ldmatrix_x4(uint32_t r[4], uint32_t addr) {
    asm volatile("ldmatrix.sync.aligned.m8n8.x4.shared.b16 {%0,%1,%2,%3}, [%4];\n"
                 : "=r"(r[0]), "=r"(r[1]), "=r"(r[2]), "=r"(r[3]) : "r"(addr));
}
__device__ __forceinline__ void ldmatrix_b(uint32_t& b00, uint32_t& b01,
                                           uint32_t& b10, uint32_t& b11, uint32_t addr) {
    asm volatile("ldmatrix.sync.aligned.m8n8.x4.trans.shared.b16 {%0,%1,%2,%3}, [%4];\n"
                 : "=r"(b00), "=r"(b01), "=r"(b10), "=r"(b11) : "r"(addr));
}
__device__ __forceinline__ void mma_16816(float c[4], const uint32_t a[4],
                                          uint32_t b0, uint32_t b1) {
    asm volatile("mma.sync.aligned.m16n8k16.row.col.f32.f16.f16.f32 "
                 "{%0,%1,%2,%3}, {%4,%5,%6,%7}, {%8,%9}, {%0,%1,%2,%3};\n"
                 : "+f"(c[0]), "+f"(c[1]), "+f"(c[2]), "+f"(c[3])
                 : "r"(a[0]), "r"(a[1]), "r"(a[2]), "r"(a[3]), "r"(b0), "r"(b1));
}
__device__ __forceinline__ void cp_async16(uint32_t dst, const void* src) {
    asm volatile("cp.async.cg.shared.global [%0], [%1], 16;\n" :: "r"(dst), "l"(src) : "memory");
}
#define CP_COMMIT() asm volatile("cp.async.commit_group;" ::: "memory")
#define CP_WAIT1()  asm volatile("cp.async.wait_group 1;" ::: "memory")
#define CP_WAIT0()  asm volatile("cp.async.wait_group 0;" ::: "memory")

// fast tanh: tanh(t) = 1 - 2/(exp(2t)+1), rel err ~1e-6
__device__ __forceinline__ float fast_tanh3(float x, float sc3) {
    float t = x * sc3;
    float e;
    asm("ex2.approx.f32 %0, %1;" : "=f"(e) : "f"(t * 2.885390082f));
    float r;
    asm("rcp.approx.f32 %0, %1;" : "=f"(r) : "f"(e + 1.0f));
    return 3.0f * (1.0f - 2.0f * r);
}

// ---------------------------------------------------------------- K2: GEMM
__device__ __forceinline__ void load_frags(uint32_t base, uint32_t af[4][4], uint32_t bf[16],
                                           const uint32_t aoff[4], const uint32_t boff[4],
                                           uint32_t ko2, uint32_t kb) {
    #pragma unroll
    for (int mi = 0; mi < 4; mi++) ldmatrix_x4(af[mi], base + aoff[mi] + ko2);
    #pragma unroll
    for (int ni = 0; ni < 4; ni++)
        ldmatrix_b(bf[ni * 4 + 0], bf[ni * 4 + 1], bf[ni * 4 + 2], bf[ni * 4 + 3],
                   base + boff[ni] + kb);
}

#define MMA_GROUP(buf)                                                          \
    do {                                                                        \
        _Pragma("unroll")                                                       \
        for (int mi = 0; mi < 4; mi++)                                          \
            _Pragma("unroll")                                                   \
            for (int nb = 0; nb < 8; nb++)                                      \
                mma_16816(acc[mi][nb], af[buf][mi],                             \
                          bf[buf][(nb >> 1) * 4 + (nb & 1) * 2],                \
                          bf[buf][(nb >> 1) * 4 + (nb & 1) * 2 + 1]);           \
    } while (0)

__global__ __launch_bounds__(128, 2) void gemm_kernel(const float* __restrict__ bias,
                                                      const float* __restrict__ scale,
                                                      float* __restrict__ out) {
    extern __shared__ __align__(16) char smem[];
    uint32_t sb;
    asm("{ .reg .u64 t; cvta.to.shared.u64 t, %1; cvt.u32.u64 %0, t; }" : "=r"(sb) : "l"(smem));

    int tid  = threadIdx.x;
    int wid  = tid >> 5;
    int lane = tid & 31;
    int wm   = wid >> 1;        // 0..1 (64 rows)
    int wn   = wid & 1;         // 0..1 (64 cols)
    int bm   = blockIdx.y;
    int bn   = blockIdx.x;

    float acc[4][8][4];
    #pragma unroll
    for (int i = 0; i < 4; i++)
        #pragma unroll
        for (int j = 0; j < 8; j++)
            #pragma unroll
            for (int k = 0; k < 4; k++) acc[i][j][k] = 0.f;

    int r8 = lane & 7;
    int q  = lane >> 3;

    uint32_t aoff[4], boff[4];
    #pragma unroll
    for (int mi = 0; mi < 4; mi++)
        aoff[mi] = (uint32_t)((wm * 64 + mi * 16 + r8 + (q & 1) * 8) * LDA + (q >> 1) * 8) * 2;
    #pragma unroll
    for (int ni = 0; ni < 4; ni++)
        boff[ni] = (uint32_t)(((q & 1) * 8 + r8) * LDB + wn * 64 + ni * 16 + (q >> 1) * 8) * 2 + A_STAGE_B;

    uint32_t as_off[8], ag_off[8], bs_off[8], bg_off[8];
    #pragma unroll
    for (int i = 0; i < 8; i++) {
        int chunk = tid + i * 128;
        int arow = chunk >> 3, ac = chunk & 7;
        as_off[i] = (uint32_t)(arow * LDA + ac * 8) * 2;
        ag_off[i] = (uint32_t)arow * (D_Z * 2) + ac * 16;
        int brow = chunk >> 4, bc = chunk & 15;
        bs_off[i] = (uint32_t)(brow * LDB + bc * 8) * 2 + A_STAGE_B;
        bg_off[i] = (uint32_t)brow * (D_MODEL * 2) + bc * 16;
    }

    const char* Abase = (const char*)(g_zn + (size_t)(bm * BM) * D_Z);
    const char* Bbase = (const char*)(g_wb + (size_t)(bn * BN));

    // preload stages 0,1
    {
        #pragma unroll
        for (int i = 0; i < 8; i++) cp_async16(sb + as_off[i], Abase + ag_off[i]);
        #pragma unroll
        for (int i = 0; i < 8; i++) cp_async16(sb + bs_off[i], Bbase + bg_off[i]);
        CP_COMMIT();
        uint32_t s1 = sb + STAGE_B;
        const char* Ag = Abase + BK * 2;
        const char* Bg = Bbase + (size_t)BK * D_MODEL * 2;
        #pragma unroll
        for (int i = 0; i < 8; i++) cp_async16(s1 + as_off[i], Ag + ag_off[i]);
        #pragma unroll
        for (int i = 0; i < 8; i++) cp_async16(s1 + bs_off[i], Bg + bg_off[i]);
        CP_COMMIT();
    }

    const char* Agp = Abase + 2 * BK * 2;
    const char* Bgp = Bbase + (size_t)2 * BK * D_MODEL * 2;

    uint32_t abase = sb;
    const uint32_t send = sb + STAGES * STAGE_B;

    uint32_t af[2][4][4];
    uint32_t bf[2][16];

    // stage 0 ready -> load ks=0 fragments into buf 0
    CP_WAIT1();
    __syncthreads();
    load_frags(abase, af[0], bf[0], aoff, boff, 0, 0);

    for (int kt = 0; kt < KITERS; kt++) {
        bool do_refill = (kt + 2 < KITERS);
        uint32_t p = abase + 2 * STAGE_B;
        uint32_t pbase = (p >= send) ? p - STAGES * STAGE_B : p;

        uint32_t nbase = abase + STAGE_B;
        if (nbase >= send) nbase = sb;

        // ---- ks0: frag-prefetch ks1, full MMA group (no loads/syncs else)
        load_frags(abase, af[1], bf[1], aoff, boff, 16 * 2, 16 * (LDB * 2));
        MMA_GROUP(0);

        // ---- ks1: frag-prefetch ks2; establish stage kt+1 under MMA backlog
        load_frags(abase, af[0], bf[0], aoff, boff, 32 * 2, 32 * (LDB * 2));
        CP_WAIT0();                 // stage kt+1 group done (committed at kt-1)
        __syncthreads();            // cross-warp visibility + slot protection
        if (do_refill) {
            #pragma unroll
            for (int i = 0; i < 4; i++) cp_async16(pbase + as_off[i], Agp + ag_off[i]);
            #pragma unroll
            for (int i = 0; i < 2; i++) cp_async16(pbase + bs_off[i], Bgp + bg_off[i]);
        }
        MMA_GROUP(1);

        // ---- ks2: frag-prefetch ks3; refill chunk 2
        load_frags(abase, af[1], bf[1], aoff, boff, 48 * 2, 48 * (LDB * 2));
        if (do_refill) {
            #pragma unroll
            for (int i = 4; i < 8; i++) cp_async16(pbase + as_off[i], Agp + ag_off[i]);
            #pragma unroll
            for (int i = 2; i < 4; i++) cp_async16(pbase + bs_off[i], Bgp + bg_off[i]);
        }
        MMA_GROUP(0);

        // ---- ks3: sync-free next-stage ks0 frag-prefetch; refill chunk 3 + commit
        if (kt + 1 < KITERS)
            load_frags(nbase, af[0], bf[0], aoff, boff, 0, 0);
        if (do_refill) {
            #pragma unroll
            for (int i = 4; i < 8; i++) cp_async16(pbase + bs_off[i], Bgp + bg_off[i]);
        }
        CP_COMMIT();
        MMA_GROUP(1);

        if (do_refill) {
            Agp += BK * 2;
            Bgp += (size_t)BK * D_MODEL * 2;
        }
        abase = nbase;
    }

    // epilogue: out = 3*tanh((acc + bias)*scale/3)
    float sc3 = scale[0] * (1.0f / 3.0f);
    int rr = lane >> 2;
    int cq = (lane & 3) * 2;

    #pragma unroll
    for (int nb = 0; nb < 8; nb++) {
        int col = bn * BN + wn * 64 + nb * 8 + cq;
        float2 bv = *(const float2*)(bias + col);
        #pragma unroll
        for (int mi = 0; mi < 4; mi++) {
            int row = bm * BM + wm * 64 + mi * 16 + rr;
            float2 o0, o1;
            o0.x = fast_tanh3(acc[mi][nb][0] + bv.x, sc3);
            o0.y = fast_tanh3(acc[mi][nb][1] + bv.y, sc3);
            o1.x = fast_tanh3(acc[mi][nb][2] + bv.x, sc3);
            o1.y = fast_tanh3(acc[mi][nb][3] + bv.y, sc3);
            *(float2*)(out + (size_t)row * D_MODEL + col)       = o0;
            *(float2*)(out + (size_t)(row + 8) * D_MODEL + col) = o1;
        }
    }
}

// ---------------------------------------------------------------- launch
extern "C" void kernel_launch(void* const* d_in, const int* in_sizes, int n_in,
                              void* d_out, int out_size) {
    const float* z     = (const float*)d_in[0];
    const float* gamma = (const float*)d_in[1];
    const float* beta  = (const float*)d_in[2];
    const float* W     = (const float*)d_in[3];
    const float* b     = (const float*)d_in[4];
    const float* scale = (const float*)d_in[5];
    float* out = (float*)d_out;
    (void)in_sizes; (void)n_in; (void)out_size;

    cudaFuncSetAttribute(gemm_kernel, cudaFuncAttributeMaxDynamicSharedMemorySize, SMEM_TOTAL);

    prep_kernel<<<LN_BLOCKS + WCONV_BLOCKS, 256>>>(z, gamma, beta, W);
    dim3 grid(D_MODEL / BN, M_ROWS / BM);   // (32, 128) = 4096 CTAs, 2/SM
    gemm_kernel<<<grid, 128, SMEM_TOTAL>>>(b, scale, out);
}